// round 13
// baseline (speedup 1.0000x reference)
#include <cuda_runtime.h>
#include <cuda_bf16.h>
#include <cstdint>

#define N_NODES  100000
#define N_EDGES  1600000
#define N_GRAPHS 512
#define DH 128
#define DL 64
#define N_LAYERS 3
#define BN_EPS 1e-5f

#define WSTRIDE 136          // bf16 elements per row in padded layouts
#define WTILE   (128 * WSTRIDE)
#define SCAN_BLOCKS ((N_NODES + 1023) / 1024)   // 98
#define N_CHUNKS 4
#define CH_ROWS  25088       // 196 * 128, last chunk = 24736 rows

// ---------------- scratch (static __device__ globals: allocation-free) -------
__device__ int   g_cnt[N_NODES];
__device__ int   g_off[N_NODES + 1];
__device__ int   g_cur[N_NODES];
__device__ int   g_csr[N_EDGES];
__device__ int   g_bsum[SCAN_BLOCKS], g_bpre[SCAN_BLOCKS];
__device__ float g_h0[N_NODES * DH];
__device__ float g_t [N_NODES * DH];
__device__ float g_xa[N_NODES * DH];
__device__ float g_xb[N_NODES * DH];
__device__ float g_stats[N_LAYERS * 2 * DH];   // per layer: [sum(128) | sq(128)]
__device__ float g_scale[DH], g_shift[DH];
__device__ float g_pool[N_GRAPHS * DH];
__device__ int   g_gstart[N_GRAPHS + 1];
__device__ float g_f1[N_GRAPHS * DL];
__device__ float g_fsum[DL], g_fsq[DL];
// pre-split, pre-transposed weights: B[n][k] = W[k][n], padded row stride 136
__device__ unsigned short g_wbh[6 * WTILE];
__device__ unsigned short g_wbl[6 * WTILE];

__device__ __forceinline__ float leaky(float x) { return x > 0.f ? x : 0.2f * x; }

// mma.sync m16n8k16 bf16 with fp32 accumulate (portable sm_80+ encoding,
// executes on the Blackwell tensor pipe as HMMA)
__device__ __forceinline__ void mma_bf16(float* d, const uint32_t* a, const uint32_t* b) {
    asm volatile(
        "mma.sync.aligned.m16n8k16.row.col.f32.bf16.bf16.f32 "
        "{%0,%1,%2,%3}, {%4,%5,%6,%7}, {%8,%9}, {%0,%1,%2,%3};"
        : "+f"(d[0]), "+f"(d[1]), "+f"(d[2]), "+f"(d[3])
        : "r"(a[0]), "r"(a[1]), "r"(a[2]), "r"(a[3]), "r"(b[0]), "r"(b[1]));
}

// ---------------- CSR build --------------------------------------------------
__global__ void k_hist(const int* __restrict__ ei) {
    int e = blockIdx.x * blockDim.x + threadIdx.x;
    if (e < N_EDGES) atomicAdd(&g_cnt[ei[N_EDGES + e]], 1);
}

// coalesced 3-phase scan: per-block exclusive scan -> block-sum scan -> apply
__global__ __launch_bounds__(1024) void k_scanA() {
    __shared__ int ss[1024];
    int tid = threadIdx.x;
    int node = blockIdx.x * 1024 + tid;
    int v = (node < N_NODES) ? g_cnt[node] : 0;
    ss[tid] = v;
    __syncthreads();
    for (int o = 1; o < 1024; o <<= 1) {
        int t = (tid >= o) ? ss[tid - o] : 0;
        __syncthreads();
        ss[tid] += t;
        __syncthreads();
    }
    if (node < N_NODES) g_off[node] = ss[tid] - v;     // exclusive within block
    if (tid == 1023) g_bsum[blockIdx.x] = ss[1023];
}

__global__ __launch_bounds__(128) void k_scanB() {
    __shared__ int ss[128];
    int tid = threadIdx.x;
    int v = (tid < SCAN_BLOCKS) ? g_bsum[tid] : 0;
    ss[tid] = v;
    __syncthreads();
    for (int o = 1; o < 128; o <<= 1) {
        int t = (tid >= o) ? ss[tid - o] : 0;
        __syncthreads();
        ss[tid] += t;
        __syncthreads();
    }
    if (tid < SCAN_BLOCKS) g_bpre[tid] = ss[tid] - v;  // exclusive block prefix
    if (tid == 127) g_off[N_NODES] = ss[127];          // total edges
}

__global__ __launch_bounds__(1024) void k_scanC() {
    int node = blockIdx.x * 1024 + threadIdx.x;
    if (node < N_NODES) {
        int o = g_off[node] + g_bpre[blockIdx.x];
        g_off[node] = o;
        g_cur[node] = o;
    }
}

__global__ void k_fill(const int* __restrict__ ei) {
    int e = blockIdx.x * blockDim.x + threadIdx.x;
    if (e < N_EDGES) {
        int s = ei[e];
        int d = ei[N_EDGES + e];
        int p = atomicAdd(&g_cur[d], 1);
        g_csr[p] = s;
    }
}

// ---------------- weight pre-conversion: W^T -> padded bf16 hi/lo -----------
__global__ void k_wconv(const float* __restrict__ W1, const float* __restrict__ W2) {
    int b = blockIdx.x;           // 0..5: layer*2 + which
    int l = b >> 1;
    const float* W = (b & 1) ? (W2 + l * DH * DH) : (W1 + l * DH * DH);
    unsigned short* bh = g_wbh + b * WTILE;
    unsigned short* bl = g_wbl + b * WTILE;
    for (int e = threadIdx.x; e < DH * DH; e += blockDim.x) {
        int n = e >> 7, k = e & 127;
        float v = W[k * DH + n];                 // B[n][k] = W[k][n]
        __nv_bfloat16 h = __float2bfloat16(v);
        float lo = v - __bfloat162float(h);
        bh[n * WSTRIDE + k] = __bfloat16_as_ushort(h);
        bl[n * WSTRIDE + k] = __bfloat16_as_ushort(__float2bfloat16(lo));
    }
}

// ---------------- graph starts via binary search (batch is sorted) ----------
__global__ void k_gstart_bs(const int* __restrict__ batch) {
    int g = blockIdx.x * blockDim.x + threadIdx.x;
    if (g > N_GRAPHS) return;
    int lo = 0, hi = N_NODES;                    // lower_bound(batch, g)
    while (lo < hi) {
        int mid = (lo + hi) >> 1;
        if (batch[mid] < g) lo = mid + 1; else hi = mid;
    }
    g_gstart[g] = lo;
}

// ---------------- aggregation: h0 = x + sum_{src in N(dst)} x[src] ----------
// warp per node over [base, end), float4 per lane, 8 rows in flight with
// next-iteration CSR index prefetch (latency-bound gather).
__global__ __launch_bounds__(256) void k_agg(const float* __restrict__ x,
                                             int base, int end) {
    int node = base + ((blockIdx.x * 256 + threadIdx.x) >> 5);
    int lane = threadIdx.x & 31;
    if (node >= end) return;
    int e0 = g_off[node], e1 = g_off[node + 1];
    const float4* xv = (const float4*)x;
    float4 acc = xv[node * 32 + lane];

    int e = e0;
    int idx[8];
    bool have = (e + 7 < e1);
    if (have) {
#pragma unroll
        for (int j = 0; j < 8; j++) idx[j] = g_csr[e + j];
    }
    while (have) {
        int en = e + 8;
        bool haveN = (en + 7 < e1);
        int nxt[8];
#pragma unroll
        for (int j = 0; j < 8; j++) nxt[j] = 0;
        if (haveN) {
#pragma unroll
            for (int j = 0; j < 8; j++) nxt[j] = g_csr[en + j];
        }
        float4 v[8];
#pragma unroll
        for (int j = 0; j < 8; j++) v[j] = xv[idx[j] * 32 + lane];
#pragma unroll
        for (int j = 0; j < 8; j++) {
            acc.x += v[j].x; acc.y += v[j].y; acc.z += v[j].z; acc.w += v[j].w;
        }
#pragma unroll
        for (int j = 0; j < 8; j++) idx[j] = nxt[j];
        e = en; have = haveN;
    }
    for (; e + 3 < e1; e += 4) {
        int a = g_csr[e], b = g_csr[e + 1], c = g_csr[e + 2], d = g_csr[e + 3];
        float4 va = xv[a * 32 + lane];
        float4 vb = xv[b * 32 + lane];
        float4 vc = xv[c * 32 + lane];
        float4 vd = xv[d * 32 + lane];
        acc.x += (va.x + vb.x) + (vc.x + vd.x);
        acc.y += (va.y + vb.y) + (vc.y + vd.y);
        acc.z += (va.z + vb.z) + (vc.z + vd.z);
        acc.w += (va.w + vb.w) + (vc.w + vd.w);
    }
    for (; e < e1; e++) {
        float4 va = xv[g_csr[e] * 32 + lane];
        acc.x += va.x; acc.y += va.y; acc.z += va.z; acc.w += va.w;
    }
    ((float4*)g_h0)[node * 32 + lane] = acc;
}

// ---------------- mma.sync GEMM ----------------------------------------------
// out = leaky( (optional BN(A)) @ W + b ) via split-bf16 HMMA, fp32 accum.
// Tile 128x128x128, 256 threads = 8 warps in 4(m) x 2(n); warp tile 32x64.
// D = Ah@Wh + Ah@Wl + Al@Wh.  rowBase allows chunked launches (pipelining).
// PRE_BN: BN scale/shift computed in-block from sumBuf/sqBuf.
// STATS : fused column sum/sumsq epilogue (atomics accumulate across chunks).
#define SAH_OFF 0
#define SAL_OFF (WTILE * 2)
#define SBH_OFF (WTILE * 4)
#define SBL_OFF (WTILE * 6)
#define SS_OFF  (WTILE * 8)
#define SQ_OFF  (WTILE * 8 + 2048)
#define MMA_SMEM (WTILE * 8 + 4096)

template <bool PRE_BN, bool STATS>
__global__ __launch_bounds__(256) void k_mma(const float* __restrict__ A,
                                             const unsigned short* __restrict__ WH,
                                             const unsigned short* __restrict__ WL,
                                             const float* __restrict__ bias,
                                             float* __restrict__ out,
                                             float* sumBuf, float* sqBuf,
                                             const float* __restrict__ gam,
                                             const float* __restrict__ bet,
                                             float invM, int rowBase, int M) {
    extern __shared__ char smc[];
    unsigned short* sAh = (unsigned short*)(smc + SAH_OFF);
    unsigned short* sAl = (unsigned short*)(smc + SAL_OFF);
    unsigned short* sBh = (unsigned short*)(smc + SBH_OFF);
    unsigned short* sBl = (unsigned short*)(smc + SBL_OFF);
    float* sS = (float*)(smc + SS_OFF);   // STATS: partial sums | PRE_BN: scale
    float* sQ = (float*)(smc + SQ_OFF);   // STATS: partial sumsq | PRE_BN: shift

    const int tid = threadIdx.x;
    const int rbase = rowBase + blockIdx.x * 128;

    if (PRE_BN) {
        if (tid < 128) {
            float mean = sumBuf[tid] * invM;
            float var = sqBuf[tid] * invM - mean * mean;
            float rstd = rsqrtf(var + BN_EPS);
            float sc = gam[tid] * rstd;
            sS[tid] = sc;
            sQ[tid] = bet[tid] - mean * sc;
        }
        __syncthreads();
    }

    // copy pre-split weights into smem (row stride already WSTRIDE)
    {
        uint4* dh = (uint4*)sBh; const uint4* sh = (const uint4*)WH;
        uint4* dl = (uint4*)sBl; const uint4* sl = (const uint4*)WL;
        for (int i = tid; i < WTILE * 2 / 16; i += 256) { dh[i] = sh[i]; dl[i] = sl[i]; }
    }

    // load + (BN) + hi/lo split A tile
#pragma unroll
    for (int i = 0; i < 32; i++) {
        int p = tid + i * 256;        // 0..8191
        int r = p >> 6;               // 0..127
        int kk = (p & 63) << 1;       // 0,2,..,126
        int row = rbase + r;
        float2 av = make_float2(0.f, 0.f);
        if (row < M) av = *(const float2*)(A + (size_t)row * DH + kk);
        if (PRE_BN) {
            av.x = av.x * sS[kk]     + sQ[kk];
            av.y = av.y * sS[kk + 1] + sQ[kk + 1];
        }
        __nv_bfloat16 h0 = __float2bfloat16(av.x);
        __nv_bfloat16 h1 = __float2bfloat16(av.y);
        __nv_bfloat16 l0 = __float2bfloat16(av.x - __bfloat162float(h0));
        __nv_bfloat16 l1 = __float2bfloat16(av.y - __bfloat162float(h1));
        uint32_t hip = (uint32_t)__bfloat16_as_ushort(h0) |
                       ((uint32_t)__bfloat16_as_ushort(h1) << 16);
        uint32_t lop = (uint32_t)__bfloat16_as_ushort(l0) |
                       ((uint32_t)__bfloat16_as_ushort(l1) << 16);
        *(uint32_t*)&sAh[r * WSTRIDE + kk] = hip;
        *(uint32_t*)&sAl[r * WSTRIDE + kk] = lop;
    }
    __syncthreads();

    const int lane = tid & 31, wid = tid >> 5;
    const int wm = wid & 3, wn = wid >> 2;
    const int g = lane >> 2, t = lane & 3;

    float acc[2][8][4];
#pragma unroll
    for (int mt = 0; mt < 2; mt++)
#pragma unroll
        for (int nt = 0; nt < 8; nt++)
#pragma unroll
            for (int q = 0; q < 4; q++) acc[mt][nt][q] = 0.f;

#pragma unroll
    for (int ks = 0; ks < 8; ks++) {
        const int KB = ks * 16 + 2 * t;
        uint32_t bh[8][2], bl[8][2];
#pragma unroll
        for (int nt = 0; nt < 8; nt++) {
            int n = wn * 64 + nt * 8 + g;
            const uint32_t* ph = (const uint32_t*)&sBh[n * WSTRIDE + KB];
            const uint32_t* pl = (const uint32_t*)&sBl[n * WSTRIDE + KB];
            bh[nt][0] = ph[0]; bh[nt][1] = ph[4];   // k and k+8
            bl[nt][0] = pl[0]; bl[nt][1] = pl[4];
        }
#pragma unroll
        for (int mt = 0; mt < 2; mt++) {
            int r = wm * 32 + mt * 16 + g;
            uint32_t ah[4], al[4];
            ah[0] = *(const uint32_t*)&sAh[r * WSTRIDE + KB];
            ah[1] = *(const uint32_t*)&sAh[(r + 8) * WSTRIDE + KB];
            ah[2] = *(const uint32_t*)&sAh[r * WSTRIDE + KB + 8];
            ah[3] = *(const uint32_t*)&sAh[(r + 8) * WSTRIDE + KB + 8];
            al[0] = *(const uint32_t*)&sAl[r * WSTRIDE + KB];
            al[1] = *(const uint32_t*)&sAl[(r + 8) * WSTRIDE + KB];
            al[2] = *(const uint32_t*)&sAl[r * WSTRIDE + KB + 8];
            al[3] = *(const uint32_t*)&sAl[(r + 8) * WSTRIDE + KB + 8];
#pragma unroll
            for (int nt = 0; nt < 8; nt++) {
                mma_bf16(acc[mt][nt], ah, bh[nt]);
                mma_bf16(acc[mt][nt], ah, bl[nt]);
                mma_bf16(acc[mt][nt], al, bh[nt]);
            }
        }
    }

    if (STATS) __syncthreads();   // sS/sQ reuse below

    // epilogue: bias + leaky + store (+ column stats)
    float2 bsv[8];
#pragma unroll
    for (int nt = 0; nt < 8; nt++)
        bsv[nt] = *(const float2*)(bias + wn * 64 + nt * 8 + 2 * t);

    float sac[8][2], qac[8][2];
#pragma unroll
    for (int nt = 0; nt < 8; nt++) {
        sac[nt][0] = sac[nt][1] = 0.f;
        qac[nt][0] = qac[nt][1] = 0.f;
    }

#pragma unroll
    for (int mt = 0; mt < 2; mt++) {
        int row0 = rbase + wm * 32 + mt * 16 + g;
        int row1 = row0 + 8;
        bool v0 = row0 < M, v1 = row1 < M;
#pragma unroll
        for (int nt = 0; nt < 8; nt++) {
            int col = wn * 64 + nt * 8 + 2 * t;
            float a0 = leaky(acc[mt][nt][0] + bsv[nt].x);
            float a1 = leaky(acc[mt][nt][1] + bsv[nt].y);
            float a2 = leaky(acc[mt][nt][2] + bsv[nt].x);
            float a3 = leaky(acc[mt][nt][3] + bsv[nt].y);
            if (v0) {
                *(float2*)(out + (size_t)row0 * DH + col) = make_float2(a0, a1);
                if (STATS) {
                    sac[nt][0] += a0; sac[nt][1] += a1;
                    qac[nt][0] += a0 * a0; qac[nt][1] += a1 * a1;
                }
            }
            if (v1) {
                *(float2*)(out + (size_t)row1 * DH + col) = make_float2(a2, a3);
                if (STATS) {
                    sac[nt][0] += a2; sac[nt][1] += a3;
                    qac[nt][0] += a2 * a2; qac[nt][1] += a3 * a3;
                }
            }
        }
    }

    if (STATS) {
#pragma unroll
        for (int nt = 0; nt < 8; nt++) {
            float s0 = sac[nt][0], s1 = sac[nt][1];
            float q0 = qac[nt][0], q1 = qac[nt][1];
#pragma unroll
            for (int o = 4; o < 32; o <<= 1) {       // reduce over g lanes
                s0 += __shfl_xor_sync(0xffffffffu, s0, o);
                s1 += __shfl_xor_sync(0xffffffffu, s1, o);
                q0 += __shfl_xor_sync(0xffffffffu, q0, o);
                q1 += __shfl_xor_sync(0xffffffffu, q1, o);
            }
            if (lane < 4) {
                int col = wn * 64 + nt * 8 + 2 * lane;
                sS[wm * 128 + col] = s0;  sS[wm * 128 + col + 1] = s1;
                sQ[wm * 128 + col] = q0;  sQ[wm * 128 + col + 1] = q1;
            }
        }
        __syncthreads();
        if (tid < 128) {
            atomicAdd(sumBuf + tid, sS[tid] + sS[128 + tid] + sS[256 + tid] + sS[384 + tid]);
        } else {
            int c = tid - 128;
            atomicAdd(sqBuf + c, sQ[c] + sQ[128 + c] + sQ[256 + c] + sQ[384 + c]);
        }
    }
}

// ---------------- pooling ----------------------------------------------------
__global__ __launch_bounds__(128) void k_pool(const float* __restrict__ x) {
    int g = blockIdx.x, c = threadIdx.x;
    int r0 = g_gstart[g], r1 = g_gstart[g + 1];
    float s = 0.f;
    for (int r = r0; r < r1; r++) s += x[r * DH + c];
    g_pool[g * DH + c] = s;
}

// ---------------- head -------------------------------------------------------
__global__ __launch_bounds__(128) void k_pool_stats(const float* __restrict__ bn_g,
                                                    const float* __restrict__ bn_b) {
    int c = threadIdx.x;
    float s = 0.f, q = 0.f;
    for (int g = 0; g < N_GRAPHS; g++) {
        float v = g_pool[g * DH + c];
        s += v; q += v * v;
    }
    float mean = s / (float)N_GRAPHS;
    float var = q / (float)N_GRAPHS - mean * mean;
    float rstd = rsqrtf(var + BN_EPS);
    float sc = bn_g[c] * rstd;
    g_scale[c] = sc;
    g_shift[c] = bn_b[c] - mean * sc;
    if (c < DL) { g_fsum[c] = 0.f; g_fsq[c] = 0.f; }
}

__global__ __launch_bounds__(64) void k_head2(const float* __restrict__ feats,
                                              const float* __restrict__ fcW,
                                              const float* __restrict__ fcb,
                                              const float* __restrict__ cW1,
                                              const float* __restrict__ cb1,
                                              const float* __restrict__ cW2,
                                              const float* __restrict__ cb2,
                                              const float* __restrict__ fW1,
                                              const float* __restrict__ fb1) {
    __shared__ float cat[DL + 8];
    __shared__ float t8[8];
    int g = blockIdx.x, j = threadIdx.x;
    if (j < 8) {
        float s = cb1[j];
        for (int i = 0; i < 7; i++) s += feats[g * 7 + i] * cW1[i * 8 + j];
        t8[j] = fmaxf(s, 0.f);
    }
    __syncthreads();
    if (j < 8) {
        float s = cb2[j];
        for (int i = 0; i < 8; i++) s += t8[i] * cW2[i * 8 + j];
        cat[DL + j] = s;
    }
    float o = fcb[j];
    for (int k = 0; k < DH; k++) {
        float a = g_pool[g * DH + k] * g_scale[k] + g_shift[k];
        o += a * fcW[k * DL + j];
    }
    cat[j] = o;
    __syncthreads();
    float s = fb1[j];
    for (int k = 0; k < DL + 8; k++) s += cat[k] * fW1[k * DL + j];
    float v = leaky(s);
    g_f1[g * DL + j] = v;
    atomicAdd(&g_fsum[j], v);
    atomicAdd(&g_fsq[j], v * v);
}

__global__ __launch_bounds__(64) void k_head4(const float* __restrict__ f_g,
                                              const float* __restrict__ f_b,
                                              const float* __restrict__ fW2,
                                              const float* __restrict__ fb2,
                                              float* __restrict__ out) {
    __shared__ float fsc[DL], fsh[DL];
    int g = blockIdx.x, j = threadIdx.x;
    {
        float mean = g_fsum[j] / (float)N_GRAPHS;
        float var = g_fsq[j] / (float)N_GRAPHS - mean * mean;
        float rstd = rsqrtf(var + BN_EPS);
        float sc = f_g[j] * rstd;
        fsc[j] = sc;
        fsh[j] = f_b[j] - mean * sc;
    }
    __syncthreads();
    float s = fb2[j];
    for (int k = 0; k < DL; k++) {
        float a = g_f1[g * DL + k] * fsc[k] + fsh[k];
        s += a * fW2[k * DL + j];
    }
    out[g * DL + j] = s;
}

// ---------------- launch -----------------------------------------------------
extern "C" void kernel_launch(void* const* d_in, const int* in_sizes, int n_in,
                              void* d_out, int out_size) {
    (void)in_sizes; (void)n_in; (void)out_size;
    const float* x      = (const float*)d_in[0];
    const int*   ei     = (const int*)  d_in[1];
    const int*   batch  = (const int*)  d_in[2];
    const float* feats  = (const float*)d_in[3];
    const float* convW1 = (const float*)d_in[4];
    const float* convb1 = (const float*)d_in[5];
    const float* convg1 = (const float*)d_in[6];
    const float* convbb1= (const float*)d_in[7];
    const float* convW2 = (const float*)d_in[8];
    const float* convb2 = (const float*)d_in[9];
    const float* bn_g   = (const float*)d_in[10];
    const float* bn_b   = (const float*)d_in[11];
    const float* fcW    = (const float*)d_in[12];
    const float* fcb    = (const float*)d_in[13];
    const float* cW1    = (const float*)d_in[14];
    const float* cb1    = (const float*)d_in[15];
    const float* cW2    = (const float*)d_in[16];
    const float* cb2    = (const float*)d_in[17];
    const float* fW1    = (const float*)d_in[18];
    const float* fb1    = (const float*)d_in[19];
    const float* f_g    = (const float*)d_in[20];
    const float* f_b    = (const float*)d_in[21];
    const float* fW2    = (const float*)d_in[22];
    const float* fb2    = (const float*)d_in[23];
    float* out = (float*)d_out;

    static bool init_done = false;
    static cudaStream_t s2 = nullptr;
    static cudaEvent_t evFork = nullptr, evJoin0 = nullptr;
    static cudaEvent_t evA[N_LAYERS * N_CHUNKS];
    static cudaEvent_t evJ[N_LAYERS];
    if (!init_done) {
        cudaFuncSetAttribute(k_mma<false, true>,
                             cudaFuncAttributeMaxDynamicSharedMemorySize, MMA_SMEM);
        cudaFuncSetAttribute(k_mma<true, false>,
                             cudaFuncAttributeMaxDynamicSharedMemorySize, MMA_SMEM);
        cudaStreamCreateWithFlags(&s2, cudaStreamNonBlocking);
        cudaEventCreateWithFlags(&evFork, cudaEventDisableTiming);
        cudaEventCreateWithFlags(&evJoin0, cudaEventDisableTiming);
        for (int i = 0; i < N_LAYERS * N_CHUNKS; i++)
            cudaEventCreateWithFlags(&evA[i], cudaEventDisableTiming);
        for (int i = 0; i < N_LAYERS; i++)
            cudaEventCreateWithFlags(&evJ[i], cudaEventDisableTiming);
        init_done = true;
    }

    float *dxa, *dxb, *dh0, *dt, *dstats;
    int *dcnt;
    unsigned short *dwh, *dwl;
    cudaGetSymbolAddress((void**)&dxa, g_xa);
    cudaGetSymbolAddress((void**)&dxb, g_xb);
    cudaGetSymbolAddress((void**)&dh0, g_h0);
    cudaGetSymbolAddress((void**)&dt,  g_t);
    cudaGetSymbolAddress((void**)&dstats, g_stats);
    cudaGetSymbolAddress((void**)&dcnt, g_cnt);
    cudaGetSymbolAddress((void**)&dwh, g_wbh);
    cudaGetSymbolAddress((void**)&dwl, g_wbl);

    // fork: side stream handles weight conversion + graph-start search
    cudaEventRecord(evFork, 0);
    cudaStreamWaitEvent(s2, evFork, 0);
    k_wconv<<<6, 256, 0, s2>>>(convW1, convW2);
    k_gstart_bs<<<3, 256, 0, s2>>>(batch);
    cudaEventRecord(evJoin0, s2);

    // main stream: CSR build (coalesced 3-phase scan)
    cudaMemsetAsync(dcnt, 0, N_NODES * sizeof(int));
    cudaMemsetAsync(dstats, 0, N_LAYERS * 2 * DH * sizeof(float));
    k_hist<<<(N_EDGES + 255) / 256, 256>>>(ei);
    k_scanA<<<SCAN_BLOCKS, 1024>>>();
    k_scanB<<<1, 128>>>();
    k_scanC<<<SCAN_BLOCKS, 1024>>>();
    k_fill<<<(N_EDGES + 255) / 256, 256>>>(ei);

    // join side stream before GEMMs (wconv) and pooling (gstart)
    cudaStreamWaitEvent(0, evJoin0, 0);

    const int GEMM_GRID = (N_NODES + 127) / 128;
    const float invM = 1.0f / (float)N_NODES;

    float* xouts[3] = {dxa, dxb, dxa};
    const float* xin = x;

    for (int l = 0; l < N_LAYERS; l++) {
        float* sumB = dstats + l * 2 * DH;
        float* sqB  = sumB + DH;

        // pipelined agg (main stream) -> GEMM1 chunks (side stream)
        for (int c = 0; c < N_CHUNKS; c++) {
            int base = c * CH_ROWS;
            if (base >= N_NODES) break;
            int end = base + CH_ROWS; if (end > N_NODES) end = N_NODES;
            int rows = end - base;
            int aggGrid = (rows * 32 + 255) / 256;
            k_agg<<<aggGrid, 256>>>(xin, base, end);
            cudaEventRecord(evA[l * N_CHUNKS + c], 0);
            cudaStreamWaitEvent(s2, evA[l * N_CHUNKS + c], 0);
            int gb = (rows + 127) / 128;
            k_mma<false, true><<<gb, 256, MMA_SMEM, s2>>>(
                dh0, dwh + (l * 2) * WTILE, dwl + (l * 2) * WTILE,
                convb1 + l * DH, dt, sumB, sqB,
                nullptr, nullptr, invM, base, end);
        }
        cudaEventRecord(evJ[l], s2);
        cudaStreamWaitEvent(0, evJ[l], 0);

        // GEMM2 (needs global BN stats) on main stream, full grid
        k_mma<true, false><<<GEMM_GRID, 256, MMA_SMEM>>>(
            dt, dwh + (l * 2 + 1) * WTILE, dwl + (l * 2 + 1) * WTILE,
            convb2 + l * DH, xouts[l], sumB, sqB,
            convg1 + l * DH, convbb1 + l * DH, invM, 0, N_NODES);
        xin = xouts[l];
    }

    // pooling via sorted-batch ranges (atomic-free)
    k_pool<<<N_GRAPHS, 128>>>(xin);

    // head
    k_pool_stats<<<1, 128>>>(bn_g, bn_b);
    k_head2<<<N_GRAPHS, 64>>>(feats, fcW, fcb, cW1, cb1, cW2, cb2, fW1, fb1);
    k_head4<<<N_GRAPHS, 64>>>(f_g, f_b, fW2, fb2, out);
}

// round 14
// speedup vs baseline: 1.2090x; 1.2090x over previous
#include <cuda_runtime.h>
#include <cuda_bf16.h>
#include <cstdint>

#define N_NODES  100000
#define N_EDGES  1600000
#define N_GRAPHS 512
#define DH 128
#define DL 64
#define N_LAYERS 3
#define BN_EPS 1e-5f

#define WSTRIDE 136          // bf16 elements per row in padded layouts
#define WTILE   (128 * WSTRIDE)
#define SCAN_BLOCKS ((N_NODES + 1023) / 1024)   // 98
#define N_TILES  ((N_NODES + 127) / 128)        // 782
#define PBLOCKS  148                            // persistent blocks = SM count

// ---------------- scratch (static __device__ globals: allocation-free) -------
__device__ int   g_cnt[N_NODES];
__device__ int   g_off[N_NODES + 1];
__device__ int   g_cur[N_NODES];
__device__ int   g_csr[N_EDGES];
__device__ int   g_bsum[SCAN_BLOCKS], g_bpre[SCAN_BLOCKS];
__device__ float g_h0[N_NODES * DH];
__device__ float g_t [N_NODES * DH];
__device__ float g_xa[N_NODES * DH];
__device__ float g_xb[N_NODES * DH];
__device__ float g_stats[N_LAYERS * 2 * DH];   // per layer: [sum(128) | sq(128)]
__device__ float g_scale[DH], g_shift[DH];
__device__ float g_pool[N_GRAPHS * DH];
__device__ int   g_gstart[N_GRAPHS + 1];
__device__ float g_f1[N_GRAPHS * DL];
__device__ float g_fsum[DL], g_fsq[DL];
// pre-split, pre-transposed weights: B[n][k] = W[k][n], padded row stride 136
__device__ unsigned short g_wbh[6 * WTILE];
__device__ unsigned short g_wbl[6 * WTILE];

__device__ __forceinline__ float leaky(float x) { return x > 0.f ? x : 0.2f * x; }

// mma.sync m16n8k16 bf16 with fp32 accumulate (portable sm_80+ encoding,
// executes on the Blackwell tensor pipe as HMMA)
__device__ __forceinline__ void mma_bf16(float* d, const uint32_t* a, const uint32_t* b) {
    asm volatile(
        "mma.sync.aligned.m16n8k16.row.col.f32.bf16.bf16.f32 "
        "{%0,%1,%2,%3}, {%4,%5,%6,%7}, {%8,%9}, {%0,%1,%2,%3};"
        : "+f"(d[0]), "+f"(d[1]), "+f"(d[2]), "+f"(d[3])
        : "r"(a[0]), "r"(a[1]), "r"(a[2]), "r"(a[3]), "r"(b[0]), "r"(b[1]));
}

// ---------------- CSR build --------------------------------------------------
__global__ void k_hist(const int* __restrict__ ei) {
    int e = blockIdx.x * blockDim.x + threadIdx.x;
    if (e < N_EDGES) atomicAdd(&g_cnt[ei[N_EDGES + e]], 1);
}

// coalesced 3-phase scan: per-block exclusive scan -> block-sum scan -> apply
__global__ __launch_bounds__(1024) void k_scanA() {
    __shared__ int ss[1024];
    int tid = threadIdx.x;
    int node = blockIdx.x * 1024 + tid;
    int v = (node < N_NODES) ? g_cnt[node] : 0;
    ss[tid] = v;
    __syncthreads();
    for (int o = 1; o < 1024; o <<= 1) {
        int t = (tid >= o) ? ss[tid - o] : 0;
        __syncthreads();
        ss[tid] += t;
        __syncthreads();
    }
    if (node < N_NODES) g_off[node] = ss[tid] - v;     // exclusive within block
    if (tid == 1023) g_bsum[blockIdx.x] = ss[1023];
}

__global__ __launch_bounds__(128) void k_scanB() {
    __shared__ int ss[128];
    int tid = threadIdx.x;
    int v = (tid < SCAN_BLOCKS) ? g_bsum[tid] : 0;
    ss[tid] = v;
    __syncthreads();
    for (int o = 1; o < 128; o <<= 1) {
        int t = (tid >= o) ? ss[tid - o] : 0;
        __syncthreads();
        ss[tid] += t;
        __syncthreads();
    }
    if (tid < SCAN_BLOCKS) g_bpre[tid] = ss[tid] - v;  // exclusive block prefix
    if (tid == 127) g_off[N_NODES] = ss[127];          // total edges
}

__global__ __launch_bounds__(1024) void k_scanC() {
    int node = blockIdx.x * 1024 + threadIdx.x;
    if (node < N_NODES) {
        int o = g_off[node] + g_bpre[blockIdx.x];
        g_off[node] = o;
        g_cur[node] = o;
    }
}

__global__ void k_fill(const int* __restrict__ ei) {
    int e = blockIdx.x * blockDim.x + threadIdx.x;
    if (e < N_EDGES) {
        int s = ei[e];
        int d = ei[N_EDGES + e];
        int p = atomicAdd(&g_cur[d], 1);
        g_csr[p] = s;
    }
}

// ---------------- weight pre-conversion: W^T -> padded bf16 hi/lo -----------
__global__ void k_wconv(const float* __restrict__ W1, const float* __restrict__ W2) {
    int b = blockIdx.x;           // 0..5: layer*2 + which
    int l = b >> 1;
    const float* W = (b & 1) ? (W2 + l * DH * DH) : (W1 + l * DH * DH);
    unsigned short* bh = g_wbh + b * WTILE;
    unsigned short* bl = g_wbl + b * WTILE;
    for (int e = threadIdx.x; e < DH * DH; e += blockDim.x) {
        int n = e >> 7, k = e & 127;
        float v = W[k * DH + n];                 // B[n][k] = W[k][n]
        __nv_bfloat16 h = __float2bfloat16(v);
        float lo = v - __bfloat162float(h);
        bh[n * WSTRIDE + k] = __bfloat16_as_ushort(h);
        bl[n * WSTRIDE + k] = __bfloat16_as_ushort(__float2bfloat16(lo));
    }
}

// ---------------- graph starts via binary search (batch is sorted) ----------
__global__ void k_gstart_bs(const int* __restrict__ batch) {
    int g = blockIdx.x * blockDim.x + threadIdx.x;
    if (g > N_GRAPHS) return;
    int lo = 0, hi = N_NODES;                    // lower_bound(batch, g)
    while (lo < hi) {
        int mid = (lo + hi) >> 1;
        if (batch[mid] < g) lo = mid + 1; else hi = mid;
    }
    g_gstart[g] = lo;
}

// ---------------- aggregation: h0 = x + sum_{src in N(dst)} x[src] ----------
// warp per node, float4 per lane, 8 rows in flight with next-iteration CSR
// index prefetch (latency-bound gather).
__global__ __launch_bounds__(256) void k_agg(const float* __restrict__ x) {
    int node = (blockIdx.x * 256 + threadIdx.x) >> 5;
    int lane = threadIdx.x & 31;
    if (node >= N_NODES) return;
    int e0 = g_off[node], e1 = g_off[node + 1];
    const float4* xv = (const float4*)x;
    float4 acc = xv[node * 32 + lane];

    int e = e0;
    int idx[8];
    bool have = (e + 7 < e1);
    if (have) {
#pragma unroll
        for (int j = 0; j < 8; j++) idx[j] = g_csr[e + j];
    }
    while (have) {
        int en = e + 8;
        bool haveN = (en + 7 < e1);
        int nxt[8];
#pragma unroll
        for (int j = 0; j < 8; j++) nxt[j] = 0;
        if (haveN) {
#pragma unroll
            for (int j = 0; j < 8; j++) nxt[j] = g_csr[en + j];
        }
        float4 v[8];
#pragma unroll
        for (int j = 0; j < 8; j++) v[j] = xv[idx[j] * 32 + lane];
#pragma unroll
        for (int j = 0; j < 8; j++) {
            acc.x += v[j].x; acc.y += v[j].y; acc.z += v[j].z; acc.w += v[j].w;
        }
#pragma unroll
        for (int j = 0; j < 8; j++) idx[j] = nxt[j];
        e = en; have = haveN;
    }
    for (; e + 3 < e1; e += 4) {
        int a = g_csr[e], b = g_csr[e + 1], c = g_csr[e + 2], d = g_csr[e + 3];
        float4 va = xv[a * 32 + lane];
        float4 vb = xv[b * 32 + lane];
        float4 vc = xv[c * 32 + lane];
        float4 vd = xv[d * 32 + lane];
        acc.x += (va.x + vb.x) + (vc.x + vd.x);
        acc.y += (va.y + vb.y) + (vc.y + vd.y);
        acc.z += (va.z + vb.z) + (vc.z + vd.z);
        acc.w += (va.w + vb.w) + (vc.w + vd.w);
    }
    for (; e < e1; e++) {
        float4 va = xv[g_csr[e] * 32 + lane];
        acc.x += va.x; acc.y += va.y; acc.z += va.z; acc.w += va.w;
    }
    ((float4*)g_h0)[node * 32 + lane] = acc;
}

// ---------------- persistent mma.sync GEMM -----------------------------------
// out = leaky( (optional BN(A)) @ W + b ) via split-bf16 HMMA, fp32 accum.
// PERSISTENT over M-tiles: grid = PBLOCKS, weights + BN constants loaded ONCE
// per block, then loop tile = bid; tile += grid over 782 row-tiles.
// Tile 128x128x128, 256 threads = 8 warps in 4(m) x 2(n); warp tile 32x64.
// D = Ah@Wh + Ah@Wl + Al@Wh.
// PRE_BN: scale/shift from sumBuf/sqBuf kept in smem for all tiles.
// STATS : column sum/sumsq accumulated in REGISTERS across tiles, single
//         atomic reduction per block at the end.
#define SAH_OFF 0
#define SAL_OFF (WTILE * 2)
#define SBH_OFF (WTILE * 4)
#define SBL_OFF (WTILE * 6)
#define SS_OFF  (WTILE * 8)
#define SQ_OFF  (WTILE * 8 + 2048)
#define MMA_SMEM (WTILE * 8 + 4096)

template <bool PRE_BN, bool STATS>
__global__ __launch_bounds__(256) void k_mma(const float* __restrict__ A,
                                             const unsigned short* __restrict__ WH,
                                             const unsigned short* __restrict__ WL,
                                             const float* __restrict__ bias,
                                             float* __restrict__ out,
                                             float* sumBuf, float* sqBuf,
                                             const float* __restrict__ gam,
                                             const float* __restrict__ bet,
                                             float invM, int M) {
    extern __shared__ char smc[];
    unsigned short* sAh = (unsigned short*)(smc + SAH_OFF);
    unsigned short* sAl = (unsigned short*)(smc + SAL_OFF);
    unsigned short* sBh = (unsigned short*)(smc + SBH_OFF);
    unsigned short* sBl = (unsigned short*)(smc + SBL_OFF);
    float* sS = (float*)(smc + SS_OFF);   // STATS: partial sums | PRE_BN: scale
    float* sQ = (float*)(smc + SQ_OFF);   // STATS: partial sumsq | PRE_BN: shift

    const int tid = threadIdx.x;
    const int lane = tid & 31, wid = tid >> 5;
    const int wm = wid & 3, wn = wid >> 2;
    const int g = lane >> 2, t = lane & 3;

    if (PRE_BN) {
        if (tid < 128) {
            float mean = sumBuf[tid] * invM;
            float var = sqBuf[tid] * invM - mean * mean;
            float rstd = rsqrtf(var + BN_EPS);
            float sc = gam[tid] * rstd;
            sS[tid] = sc;
            sQ[tid] = bet[tid] - mean * sc;
        }
    }

    // copy pre-split weights into smem ONCE (row stride already WSTRIDE)
    {
        uint4* dh = (uint4*)sBh; const uint4* sh = (const uint4*)WH;
        uint4* dl = (uint4*)sBl; const uint4* sl = (const uint4*)WL;
        for (int i = tid; i < WTILE * 2 / 16; i += 256) { dh[i] = sh[i]; dl[i] = sl[i]; }
    }
    __syncthreads();

    // bias fragment (constant across tiles)
    float2 bsv[8];
#pragma unroll
    for (int nt = 0; nt < 8; nt++)
        bsv[nt] = *(const float2*)(bias + wn * 64 + nt * 8 + 2 * t);

    // cross-tile stats accumulators (registers)
    float sac[8][2], qac[8][2];
    if (STATS) {
#pragma unroll
        for (int nt = 0; nt < 8; nt++) {
            sac[nt][0] = sac[nt][1] = 0.f;
            qac[nt][0] = qac[nt][1] = 0.f;
        }
    }

    for (int tile = blockIdx.x; tile < N_TILES; tile += gridDim.x) {
        const int rbase = tile * 128;

        // load + (BN) + hi/lo split A tile
#pragma unroll
        for (int i = 0; i < 32; i++) {
            int p = tid + i * 256;        // 0..8191
            int r = p >> 6;               // 0..127
            int kk = (p & 63) << 1;       // 0,2,..,126
            int row = rbase + r;
            float2 av = make_float2(0.f, 0.f);
            if (row < M) av = *(const float2*)(A + (size_t)row * DH + kk);
            if (PRE_BN) {
                av.x = av.x * sS[kk]     + sQ[kk];
                av.y = av.y * sS[kk + 1] + sQ[kk + 1];
            }
            __nv_bfloat16 h0 = __float2bfloat16(av.x);
            __nv_bfloat16 h1 = __float2bfloat16(av.y);
            __nv_bfloat16 l0 = __float2bfloat16(av.x - __bfloat162float(h0));
            __nv_bfloat16 l1 = __float2bfloat16(av.y - __bfloat162float(h1));
            uint32_t hip = (uint32_t)__bfloat16_as_ushort(h0) |
                           ((uint32_t)__bfloat16_as_ushort(h1) << 16);
            uint32_t lop = (uint32_t)__bfloat16_as_ushort(l0) |
                           ((uint32_t)__bfloat16_as_ushort(l1) << 16);
            *(uint32_t*)&sAh[r * WSTRIDE + kk] = hip;
            *(uint32_t*)&sAl[r * WSTRIDE + kk] = lop;
        }
        __syncthreads();

        float acc[2][8][4];
#pragma unroll
        for (int mt = 0; mt < 2; mt++)
#pragma unroll
            for (int nt = 0; nt < 8; nt++)
#pragma unroll
                for (int q = 0; q < 4; q++) acc[mt][nt][q] = 0.f;

#pragma unroll
        for (int ks = 0; ks < 8; ks++) {
            const int KB = ks * 16 + 2 * t;
            uint32_t bh[8][2], bl[8][2];
#pragma unroll
            for (int nt = 0; nt < 8; nt++) {
                int n = wn * 64 + nt * 8 + g;
                const uint32_t* ph = (const uint32_t*)&sBh[n * WSTRIDE + KB];
                const uint32_t* pl = (const uint32_t*)&sBl[n * WSTRIDE + KB];
                bh[nt][0] = ph[0]; bh[nt][1] = ph[4];   // k and k+8
                bl[nt][0] = pl[0]; bl[nt][1] = pl[4];
            }
#pragma unroll
            for (int mt = 0; mt < 2; mt++) {
                int r = wm * 32 + mt * 16 + g;
                uint32_t ah[4], al[4];
                ah[0] = *(const uint32_t*)&sAh[r * WSTRIDE + KB];
                ah[1] = *(const uint32_t*)&sAh[(r + 8) * WSTRIDE + KB];
                ah[2] = *(const uint32_t*)&sAh[r * WSTRIDE + KB + 8];
                ah[3] = *(const uint32_t*)&sAh[(r + 8) * WSTRIDE + KB + 8];
                al[0] = *(const uint32_t*)&sAl[r * WSTRIDE + KB];
                al[1] = *(const uint32_t*)&sAl[(r + 8) * WSTRIDE + KB];
                al[2] = *(const uint32_t*)&sAl[r * WSTRIDE + KB + 8];
                al[3] = *(const uint32_t*)&sAl[(r + 8) * WSTRIDE + KB + 8];
#pragma unroll
                for (int nt = 0; nt < 8; nt++) {
                    mma_bf16(acc[mt][nt], ah, bh[nt]);
                    mma_bf16(acc[mt][nt], ah, bl[nt]);
                    mma_bf16(acc[mt][nt], al, bh[nt]);
                }
            }
        }

        // epilogue: bias + leaky + store (+ register stats accumulation)
#pragma unroll
        for (int mt = 0; mt < 2; mt++) {
            int row0 = rbase + wm * 32 + mt * 16 + g;
            int row1 = row0 + 8;
            bool v0 = row0 < M, v1 = row1 < M;
#pragma unroll
            for (int nt = 0; nt < 8; nt++) {
                int col = wn * 64 + nt * 8 + 2 * t;
                float a0 = leaky(acc[mt][nt][0] + bsv[nt].x);
                float a1 = leaky(acc[mt][nt][1] + bsv[nt].y);
                float a2 = leaky(acc[mt][nt][2] + bsv[nt].x);
                float a3 = leaky(acc[mt][nt][3] + bsv[nt].y);
                if (v0) {
                    *(float2*)(out + (size_t)row0 * DH + col) = make_float2(a0, a1);
                    if (STATS) {
                        sac[nt][0] += a0; sac[nt][1] += a1;
                        qac[nt][0] += a0 * a0; qac[nt][1] += a1 * a1;
                    }
                }
                if (v1) {
                    *(float2*)(out + (size_t)row1 * DH + col) = make_float2(a2, a3);
                    if (STATS) {
                        sac[nt][0] += a2; sac[nt][1] += a3;
                        qac[nt][0] += a2 * a2; qac[nt][1] += a3 * a3;
                    }
                }
            }
        }
        __syncthreads();   // protect sAh/sAl before next tile overwrites
    }

    if (STATS) {
        // block-level reduction of cross-tile register stats, one atomic set
#pragma unroll
        for (int nt = 0; nt < 8; nt++) {
            float s0 = sac[nt][0], s1 = sac[nt][1];
            float q0 = qac[nt][0], q1 = qac[nt][1];
#pragma unroll
            for (int o = 4; o < 32; o <<= 1) {       // reduce over g lanes
                s0 += __shfl_xor_sync(0xffffffffu, s0, o);
                s1 += __shfl_xor_sync(0xffffffffu, s1, o);
                q0 += __shfl_xor_sync(0xffffffffu, q0, o);
                q1 += __shfl_xor_sync(0xffffffffu, q1, o);
            }
            if (lane < 4) {
                int col = wn * 64 + nt * 8 + 2 * lane;
                sS[wm * 128 + col] = s0;  sS[wm * 128 + col + 1] = s1;
                sQ[wm * 128 + col] = q0;  sQ[wm * 128 + col + 1] = q1;
            }
        }
        __syncthreads();
        if (tid < 128) {
            atomicAdd(sumBuf + tid, sS[tid] + sS[128 + tid] + sS[256 + tid] + sS[384 + tid]);
        } else {
            int c = tid - 128;
            atomicAdd(sqBuf + c, sQ[c] + sQ[128 + c] + sQ[256 + c] + sQ[384 + c]);
        }
    }
}

// ---------------- pooling ----------------------------------------------------
__global__ __launch_bounds__(128) void k_pool(const float* __restrict__ x) {
    int g = blockIdx.x, c = threadIdx.x;
    int r0 = g_gstart[g], r1 = g_gstart[g + 1];
    float s = 0.f;
    for (int r = r0; r < r1; r++) s += x[r * DH + c];
    g_pool[g * DH + c] = s;
}

// ---------------- head -------------------------------------------------------
__global__ __launch_bounds__(128) void k_pool_stats(const float* __restrict__ bn_g,
                                                    const float* __restrict__ bn_b) {
    int c = threadIdx.x;
    float s = 0.f, q = 0.f;
    for (int g = 0; g < N_GRAPHS; g++) {
        float v = g_pool[g * DH + c];
        s += v; q += v * v;
    }
    float mean = s / (float)N_GRAPHS;
    float var = q / (float)N_GRAPHS - mean * mean;
    float rstd = rsqrtf(var + BN_EPS);
    float sc = bn_g[c] * rstd;
    g_scale[c] = sc;
    g_shift[c] = bn_b[c] - mean * sc;
    if (c < DL) { g_fsum[c] = 0.f; g_fsq[c] = 0.f; }
}

__global__ __launch_bounds__(64) void k_head2(const float* __restrict__ feats,
                                              const float* __restrict__ fcW,
                                              const float* __restrict__ fcb,
                                              const float* __restrict__ cW1,
                                              const float* __restrict__ cb1,
                                              const float* __restrict__ cW2,
                                              const float* __restrict__ cb2,
                                              const float* __restrict__ fW1,
                                              const float* __restrict__ fb1) {
    __shared__ float cat[DL + 8];
    __shared__ float t8[8];
    int g = blockIdx.x, j = threadIdx.x;
    if (j < 8) {
        float s = cb1[j];
        for (int i = 0; i < 7; i++) s += feats[g * 7 + i] * cW1[i * 8 + j];
        t8[j] = fmaxf(s, 0.f);
    }
    __syncthreads();
    if (j < 8) {
        float s = cb2[j];
        for (int i = 0; i < 8; i++) s += t8[i] * cW2[i * 8 + j];
        cat[DL + j] = s;
    }
    float o = fcb[j];
    for (int k = 0; k < DH; k++) {
        float a = g_pool[g * DH + k] * g_scale[k] + g_shift[k];
        o += a * fcW[k * DL + j];
    }
    cat[j] = o;
    __syncthreads();
    float s = fb1[j];
    for (int k = 0; k < DL + 8; k++) s += cat[k] * fW1[k * DL + j];
    float v = leaky(s);
    g_f1[g * DL + j] = v;
    atomicAdd(&g_fsum[j], v);
    atomicAdd(&g_fsq[j], v * v);
}

__global__ __launch_bounds__(64) void k_head4(const float* __restrict__ f_g,
                                              const float* __restrict__ f_b,
                                              const float* __restrict__ fW2,
                                              const float* __restrict__ fb2,
                                              float* __restrict__ out) {
    __shared__ float fsc[DL], fsh[DL];
    int g = blockIdx.x, j = threadIdx.x;
    {
        float mean = g_fsum[j] / (float)N_GRAPHS;
        float var = g_fsq[j] / (float)N_GRAPHS - mean * mean;
        float rstd = rsqrtf(var + BN_EPS);
        float sc = f_g[j] * rstd;
        fsc[j] = sc;
        fsh[j] = f_b[j] - mean * sc;
    }
    __syncthreads();
    float s = fb2[j];
    for (int k = 0; k < DL; k++) {
        float a = g_f1[g * DL + k] * fsc[k] + fsh[k];
        s += a * fW2[k * DL + j];
    }
    out[g * DL + j] = s;
}

// ---------------- launch -----------------------------------------------------
extern "C" void kernel_launch(void* const* d_in, const int* in_sizes, int n_in,
                              void* d_out, int out_size) {
    (void)in_sizes; (void)n_in; (void)out_size;
    const float* x      = (const float*)d_in[0];
    const int*   ei     = (const int*)  d_in[1];
    const int*   batch  = (const int*)  d_in[2];
    const float* feats  = (const float*)d_in[3];
    const float* convW1 = (const float*)d_in[4];
    const float* convb1 = (const float*)d_in[5];
    const float* convg1 = (const float*)d_in[6];
    const float* convbb1= (const float*)d_in[7];
    const float* convW2 = (const float*)d_in[8];
    const float* convb2 = (const float*)d_in[9];
    const float* bn_g   = (const float*)d_in[10];
    const float* bn_b   = (const float*)d_in[11];
    const float* fcW    = (const float*)d_in[12];
    const float* fcb    = (const float*)d_in[13];
    const float* cW1    = (const float*)d_in[14];
    const float* cb1    = (const float*)d_in[15];
    const float* cW2    = (const float*)d_in[16];
    const float* cb2    = (const float*)d_in[17];
    const float* fW1    = (const float*)d_in[18];
    const float* fb1    = (const float*)d_in[19];
    const float* f_g    = (const float*)d_in[20];
    const float* f_b    = (const float*)d_in[21];
    const float* fW2    = (const float*)d_in[22];
    const float* fb2    = (const float*)d_in[23];
    float* out = (float*)d_out;

    static bool init_done = false;
    static cudaStream_t s2 = nullptr;
    static cudaEvent_t evFork = nullptr, evJoin0 = nullptr;
    if (!init_done) {
        cudaFuncSetAttribute(k_mma<false, true>,
                             cudaFuncAttributeMaxDynamicSharedMemorySize, MMA_SMEM);
        cudaFuncSetAttribute(k_mma<true, false>,
                             cudaFuncAttributeMaxDynamicSharedMemorySize, MMA_SMEM);
        cudaStreamCreateWithFlags(&s2, cudaStreamNonBlocking);
        cudaEventCreateWithFlags(&evFork, cudaEventDisableTiming);
        cudaEventCreateWithFlags(&evJoin0, cudaEventDisableTiming);
        init_done = true;
    }

    float *dxa, *dxb, *dh0, *dt, *dstats;
    int *dcnt;
    unsigned short *dwh, *dwl;
    cudaGetSymbolAddress((void**)&dxa, g_xa);
    cudaGetSymbolAddress((void**)&dxb, g_xb);
    cudaGetSymbolAddress((void**)&dh0, g_h0);
    cudaGetSymbolAddress((void**)&dt,  g_t);
    cudaGetSymbolAddress((void**)&dstats, g_stats);
    cudaGetSymbolAddress((void**)&dcnt, g_cnt);
    cudaGetSymbolAddress((void**)&dwh, g_wbh);
    cudaGetSymbolAddress((void**)&dwl, g_wbl);

    // fork: side stream handles weight conversion + graph-start search
    cudaEventRecord(evFork, 0);
    cudaStreamWaitEvent(s2, evFork, 0);
    k_wconv<<<6, 256, 0, s2>>>(convW1, convW2);
    k_gstart_bs<<<3, 256, 0, s2>>>(batch);
    cudaEventRecord(evJoin0, s2);

    // main stream: CSR build (coalesced 3-phase scan)
    cudaMemsetAsync(dcnt, 0, N_NODES * sizeof(int));
    cudaMemsetAsync(dstats, 0, N_LAYERS * 2 * DH * sizeof(float));
    k_hist<<<(N_EDGES + 255) / 256, 256>>>(ei);
    k_scanA<<<SCAN_BLOCKS, 1024>>>();
    k_scanB<<<1, 128>>>();
    k_scanC<<<SCAN_BLOCKS, 1024>>>();
    k_fill<<<(N_EDGES + 255) / 256, 256>>>(ei);

    // join side stream before GEMMs (wconv) and pooling (gstart)
    cudaStreamWaitEvent(0, evJoin0, 0);

    const int AGG_GRID = (N_NODES * 32 + 255) / 256;
    const float invM = 1.0f / (float)N_NODES;

    float* xouts[3] = {dxa, dxb, dxa};
    const float* xin = x;

    for (int l = 0; l < N_LAYERS; l++) {
        float* sumB = dstats + l * 2 * DH;
        float* sqB  = sumB + DH;
        k_agg<<<AGG_GRID, 256>>>(xin);
        k_mma<false, true><<<PBLOCKS, 256, MMA_SMEM>>>(
            dh0, dwh + (l * 2) * WTILE, dwl + (l * 2) * WTILE,
            convb1 + l * DH, dt, sumB, sqB,
            nullptr, nullptr, invM, N_NODES);
        k_mma<true, false><<<PBLOCKS, 256, MMA_SMEM>>>(
            dt, dwh + (l * 2 + 1) * WTILE, dwl + (l * 2 + 1) * WTILE,
            convb2 + l * DH, xouts[l], sumB, sqB,
            convg1 + l * DH, convbb1 + l * DH, invM, N_NODES);
        xin = xouts[l];
    }

    // pooling via sorted-batch ranges (atomic-free)
    k_pool<<<N_GRAPHS, 128>>>(xin);

    // head
    k_pool_stats<<<1, 128>>>(bn_g, bn_b);
    k_head2<<<N_GRAPHS, 64>>>(feats, fcW, fcb, cW1, cb1, cW2, cb2, fW1, fb1);
    k_head4<<<N_GRAPHS, 64>>>(f_g, f_b, fW2, fb2, out);
}

// round 16
// speedup vs baseline: 1.2135x; 1.0037x over previous
#include <cuda_runtime.h>
#include <cuda_bf16.h>
#include <cstdint>

#define N_NODES  100000
#define N_EDGES  1600000
#define N_GRAPHS 512
#define DH 128
#define DL 64
#define N_LAYERS 3
#define BN_EPS 1e-5f

#define WSTRIDE 136          // bf16 elements per row in padded layouts
#define WTILE   (128 * WSTRIDE)
#define SCAN_BLOCKS ((N_NODES + 1023) / 1024)   // 98
#define N_TILES  ((N_NODES + 127) / 128)        // 782
#define PBLOCKS  148                            // persistent blocks = SM count

// ---------------- scratch (static __device__ globals: allocation-free) -------
__device__ int   g_cnt[N_NODES];
__device__ int   g_off[N_NODES + 1];
__device__ int   g_cur[N_NODES];
__device__ int   g_csr[N_EDGES];
__device__ int   g_bsum[SCAN_BLOCKS], g_bpre[SCAN_BLOCKS];
__device__ float g_h0[N_NODES * DH];
__device__ float g_t [N_NODES * DH];
__device__ float g_xa[N_NODES * DH];
__device__ float g_xb[N_NODES * DH];
__device__ float g_stats[N_LAYERS * 2 * DH];   // per layer: [sum(128) | sq(128)]
__device__ float g_scale[DH], g_shift[DH];
__device__ float g_pool[N_GRAPHS * DH];
__device__ int   g_gstart[N_GRAPHS + 1];
__device__ float g_f1[N_GRAPHS * DL];
__device__ float g_fsum[DL], g_fsq[DL];
// pre-split, pre-transposed weights: B[n][k] = W[k][n], padded row stride 136
__device__ unsigned short g_wbh[6 * WTILE];
__device__ unsigned short g_wbl[6 * WTILE];

__device__ __forceinline__ float leaky(float x) { return x > 0.f ? x : 0.2f * x; }

// mma.sync m16n8k16 bf16 with fp32 accumulate (portable sm_80+ encoding,
// executes on the Blackwell tensor pipe as HMMA)
__device__ __forceinline__ void mma_bf16(float* d, const uint32_t* a, const uint32_t* b) {
    asm volatile(
        "mma.sync.aligned.m16n8k16.row.col.f32.bf16.bf16.f32 "
        "{%0,%1,%2,%3}, {%4,%5,%6,%7}, {%8,%9}, {%0,%1,%2,%3};"
        : "+f"(d[0]), "+f"(d[1]), "+f"(d[2]), "+f"(d[3])
        : "r"(a[0]), "r"(a[1]), "r"(a[2]), "r"(a[3]), "r"(b[0]), "r"(b[1]));
}

// ---------------- CSR build --------------------------------------------------
__global__ void k_hist(const int* __restrict__ ei) {
    int e = blockIdx.x * blockDim.x + threadIdx.x;
    if (e < N_EDGES) atomicAdd(&g_cnt[ei[N_EDGES + e]], 1);
}

// coalesced 3-phase scan: per-block exclusive scan -> block-sum scan -> apply
__global__ __launch_bounds__(1024) void k_scanA() {
    __shared__ int ss[1024];
    int tid = threadIdx.x;
    int node = blockIdx.x * 1024 + tid;
    int v = (node < N_NODES) ? g_cnt[node] : 0;
    ss[tid] = v;
    __syncthreads();
    for (int o = 1; o < 1024; o <<= 1) {
        int t = (tid >= o) ? ss[tid - o] : 0;
        __syncthreads();
        ss[tid] += t;
        __syncthreads();
    }
    if (node < N_NODES) g_off[node] = ss[tid] - v;     // exclusive within block
    if (tid == 1023) g_bsum[blockIdx.x] = ss[1023];
}

__global__ __launch_bounds__(128) void k_scanB() {
    __shared__ int ss[128];
    int tid = threadIdx.x;
    int v = (tid < SCAN_BLOCKS) ? g_bsum[tid] : 0;
    ss[tid] = v;
    __syncthreads();
    for (int o = 1; o < 128; o <<= 1) {
        int t = (tid >= o) ? ss[tid - o] : 0;
        __syncthreads();
        ss[tid] += t;
        __syncthreads();
    }
    if (tid < SCAN_BLOCKS) g_bpre[tid] = ss[tid] - v;  // exclusive block prefix
    if (tid == 127) g_off[N_NODES] = ss[127];          // total edges
}

__global__ __launch_bounds__(1024) void k_scanC() {
    int node = blockIdx.x * 1024 + threadIdx.x;
    if (node < N_NODES) {
        int o = g_off[node] + g_bpre[blockIdx.x];
        g_off[node] = o;
        g_cur[node] = o;
    }
}

__global__ void k_fill(const int* __restrict__ ei) {
    int e = blockIdx.x * blockDim.x + threadIdx.x;
    if (e < N_EDGES) {
        int s = ei[e];
        int d = ei[N_EDGES + e];
        int p = atomicAdd(&g_cur[d], 1);
        g_csr[p] = s;
    }
}

// ---------------- weight pre-conversion: W^T -> padded bf16 hi/lo -----------
__global__ void k_wconv(const float* __restrict__ W1, const float* __restrict__ W2) {
    int b = blockIdx.x;           // 0..5: layer*2 + which
    int l = b >> 1;
    const float* W = (b & 1) ? (W2 + l * DH * DH) : (W1 + l * DH * DH);
    unsigned short* bh = g_wbh + b * WTILE;
    unsigned short* bl = g_wbl + b * WTILE;
    for (int e = threadIdx.x; e < DH * DH; e += blockDim.x) {
        int n = e >> 7, k = e & 127;
        float v = W[k * DH + n];                 // B[n][k] = W[k][n]
        __nv_bfloat16 h = __float2bfloat16(v);
        float lo = v - __bfloat162float(h);
        bh[n * WSTRIDE + k] = __bfloat16_as_ushort(h);
        bl[n * WSTRIDE + k] = __bfloat16_as_ushort(__float2bfloat16(lo));
    }
}

// ---------------- graph starts via binary search (batch is sorted) ----------
__global__ void k_gstart_bs(const int* __restrict__ batch) {
    int g = blockIdx.x * blockDim.x + threadIdx.x;
    if (g > N_GRAPHS) return;
    int lo = 0, hi = N_NODES;                    // lower_bound(batch, g)
    while (lo < hi) {
        int mid = (lo + hi) >> 1;
        if (batch[mid] < g) lo = mid + 1; else hi = mid;
    }
    g_gstart[g] = lo;
}

// ---------------- aggregation: h0 = x + sum_{src in N(dst)} x[src] ----------
// warp per node, float4 per lane, 8 rows in flight with next-iteration CSR
// index prefetch (latency-bound gather).
__global__ __launch_bounds__(256) void k_agg(const float* __restrict__ x) {
    int node = (blockIdx.x * 256 + threadIdx.x) >> 5;
    int lane = threadIdx.x & 31;
    if (node >= N_NODES) return;
    int e0 = g_off[node], e1 = g_off[node + 1];
    const float4* xv = (const float4*)x;
    float4 acc = xv[node * 32 + lane];

    int e = e0;
    int idx[8];
    bool have = (e + 7 < e1);
    if (have) {
#pragma unroll
        for (int j = 0; j < 8; j++) idx[j] = g_csr[e + j];
    }
    while (have) {
        int en = e + 8;
        bool haveN = (en + 7 < e1);
        int nxt[8];
#pragma unroll
        for (int j = 0; j < 8; j++) nxt[j] = 0;
        if (haveN) {
#pragma unroll
            for (int j = 0; j < 8; j++) nxt[j] = g_csr[en + j];
        }
        float4 v[8];
#pragma unroll
        for (int j = 0; j < 8; j++) v[j] = xv[idx[j] * 32 + lane];
#pragma unroll
        for (int j = 0; j < 8; j++) {
            acc.x += v[j].x; acc.y += v[j].y; acc.z += v[j].z; acc.w += v[j].w;
        }
#pragma unroll
        for (int j = 0; j < 8; j++) idx[j] = nxt[j];
        e = en; have = haveN;
    }
    for (; e + 3 < e1; e += 4) {
        int a = g_csr[e], b = g_csr[e + 1], c = g_csr[e + 2], d = g_csr[e + 3];
        float4 va = xv[a * 32 + lane];
        float4 vb = xv[b * 32 + lane];
        float4 vc = xv[c * 32 + lane];
        float4 vd = xv[d * 32 + lane];
        acc.x += (va.x + vb.x) + (vc.x + vd.x);
        acc.y += (va.y + vb.y) + (vc.y + vd.y);
        acc.z += (va.z + vb.z) + (vc.z + vd.z);
        acc.w += (va.w + vb.w) + (vc.w + vd.w);
    }
    for (; e < e1; e++) {
        float4 va = xv[g_csr[e] * 32 + lane];
        acc.x += va.x; acc.y += va.y; acc.z += va.z; acc.w += va.w;
    }
    ((float4*)g_h0)[node * 32 + lane] = acc;
}

// ---------------- persistent mma.sync GEMM -----------------------------------
// out = leaky( (optional BN(A)) @ W + b ) via split-bf16 HMMA, fp32 accum.
// PERSISTENT over M-tiles: grid = PBLOCKS, weights + BN constants loaded ONCE
// per block, then loop tile = bid; tile += grid over 782 row-tiles.
// Tile 128x128x128, 256 threads = 8 warps in 4(m) x 2(n); warp tile 32x64.
// D = Ah@Wh + Ah@Wl + Al@Wh.
// PRE_BN: scale/shift from sumBuf/sqBuf kept in smem for all tiles.
// STATS : column sum/sumsq accumulated in REGISTERS across tiles, single
//         atomic reduction per block at the end.
#define SAH_OFF 0
#define SAL_OFF (WTILE * 2)
#define SBH_OFF (WTILE * 4)
#define SBL_OFF (WTILE * 6)
#define SS_OFF  (WTILE * 8)
#define SQ_OFF  (WTILE * 8 + 2048)
#define MMA_SMEM (WTILE * 8 + 4096)

template <bool PRE_BN, bool STATS>
__global__ __launch_bounds__(256) void k_mma(const float* __restrict__ A,
                                             const unsigned short* __restrict__ WH,
                                             const unsigned short* __restrict__ WL,
                                             const float* __restrict__ bias,
                                             float* __restrict__ out,
                                             float* sumBuf, float* sqBuf,
                                             const float* __restrict__ gam,
                                             const float* __restrict__ bet,
                                             float invM, int M) {
    extern __shared__ char smc[];
    unsigned short* sAh = (unsigned short*)(smc + SAH_OFF);
    unsigned short* sAl = (unsigned short*)(smc + SAL_OFF);
    unsigned short* sBh = (unsigned short*)(smc + SBH_OFF);
    unsigned short* sBl = (unsigned short*)(smc + SBL_OFF);
    float* sS = (float*)(smc + SS_OFF);   // STATS: partial sums | PRE_BN: scale
    float* sQ = (float*)(smc + SQ_OFF);   // STATS: partial sumsq | PRE_BN: shift

    const int tid = threadIdx.x;
    const int lane = tid & 31, wid = tid >> 5;
    const int wm = wid & 3, wn = wid >> 2;
    const int g = lane >> 2, t = lane & 3;

    if (PRE_BN) {
        if (tid < 128) {
            float mean = sumBuf[tid] * invM;
            float var = sqBuf[tid] * invM - mean * mean;
            float rstd = rsqrtf(var + BN_EPS);
            float sc = gam[tid] * rstd;
            sS[tid] = sc;
            sQ[tid] = bet[tid] - mean * sc;
        }
    }

    // copy pre-split weights into smem ONCE (row stride already WSTRIDE)
    {
        uint4* dh = (uint4*)sBh; const uint4* sh = (const uint4*)WH;
        uint4* dl = (uint4*)sBl; const uint4* sl = (const uint4*)WL;
        for (int i = tid; i < WTILE * 2 / 16; i += 256) { dh[i] = sh[i]; dl[i] = sl[i]; }
    }
    __syncthreads();

    // bias fragment (constant across tiles)
    float2 bsv[8];
#pragma unroll
    for (int nt = 0; nt < 8; nt++)
        bsv[nt] = *(const float2*)(bias + wn * 64 + nt * 8 + 2 * t);

    // cross-tile stats accumulators (registers)
    float sac[8][2], qac[8][2];
    if (STATS) {
#pragma unroll
        for (int nt = 0; nt < 8; nt++) {
            sac[nt][0] = sac[nt][1] = 0.f;
            qac[nt][0] = qac[nt][1] = 0.f;
        }
    }

    for (int tile = blockIdx.x; tile < N_TILES; tile += gridDim.x) {
        const int rbase = tile * 128;

        // load + (BN) + hi/lo split A tile
#pragma unroll
        for (int i = 0; i < 32; i++) {
            int p = tid + i * 256;        // 0..8191
            int r = p >> 6;               // 0..127
            int kk = (p & 63) << 1;       // 0,2,..,126
            int row = rbase + r;
            float2 av = make_float2(0.f, 0.f);
            if (row < M) av = *(const float2*)(A + (size_t)row * DH + kk);
            if (PRE_BN) {
                av.x = av.x * sS[kk]     + sQ[kk];
                av.y = av.y * sS[kk + 1] + sQ[kk + 1];
            }
            __nv_bfloat16 h0 = __float2bfloat16(av.x);
            __nv_bfloat16 h1 = __float2bfloat16(av.y);
            __nv_bfloat16 l0 = __float2bfloat16(av.x - __bfloat162float(h0));
            __nv_bfloat16 l1 = __float2bfloat16(av.y - __bfloat162float(h1));
            uint32_t hip = (uint32_t)__bfloat16_as_ushort(h0) |
                           ((uint32_t)__bfloat16_as_ushort(h1) << 16);
            uint32_t lop = (uint32_t)__bfloat16_as_ushort(l0) |
                           ((uint32_t)__bfloat16_as_ushort(l1) << 16);
            *(uint32_t*)&sAh[r * WSTRIDE + kk] = hip;
            *(uint32_t*)&sAl[r * WSTRIDE + kk] = lop;
        }
        __syncthreads();

        float acc[2][8][4];
#pragma unroll
        for (int mt = 0; mt < 2; mt++)
#pragma unroll
            for (int nt = 0; nt < 8; nt++)
#pragma unroll
                for (int q = 0; q < 4; q++) acc[mt][nt][q] = 0.f;

#pragma unroll
        for (int ks = 0; ks < 8; ks++) {
            const int KB = ks * 16 + 2 * t;
            uint32_t bh[8][2], bl[8][2];
#pragma unroll
            for (int nt = 0; nt < 8; nt++) {
                int n = wn * 64 + nt * 8 + g;
                const uint32_t* ph = (const uint32_t*)&sBh[n * WSTRIDE + KB];
                const uint32_t* pl = (const uint32_t*)&sBl[n * WSTRIDE + KB];
                bh[nt][0] = ph[0]; bh[nt][1] = ph[4];   // k and k+8
                bl[nt][0] = pl[0]; bl[nt][1] = pl[4];
            }
#pragma unroll
            for (int mt = 0; mt < 2; mt++) {
                int r = wm * 32 + mt * 16 + g;
                uint32_t ah[4], al[4];
                ah[0] = *(const uint32_t*)&sAh[r * WSTRIDE + KB];
                ah[1] = *(const uint32_t*)&sAh[(r + 8) * WSTRIDE + KB];
                ah[2] = *(const uint32_t*)&sAh[r * WSTRIDE + KB + 8];
                ah[3] = *(const uint32_t*)&sAh[(r + 8) * WSTRIDE + KB + 8];
                al[0] = *(const uint32_t*)&sAl[r * WSTRIDE + KB];
                al[1] = *(const uint32_t*)&sAl[(r + 8) * WSTRIDE + KB];
                al[2] = *(const uint32_t*)&sAl[r * WSTRIDE + KB + 8];
                al[3] = *(const uint32_t*)&sAl[(r + 8) * WSTRIDE + KB + 8];
#pragma unroll
                for (int nt = 0; nt < 8; nt++) {
                    mma_bf16(acc[mt][nt], ah, bh[nt]);
                    mma_bf16(acc[mt][nt], ah, bl[nt]);
                    mma_bf16(acc[mt][nt], al, bh[nt]);
                }
            }
        }

        // epilogue: bias + leaky + store (+ register stats accumulation)
#pragma unroll
        for (int mt = 0; mt < 2; mt++) {
            int row0 = rbase + wm * 32 + mt * 16 + g;
            int row1 = row0 + 8;
            bool v0 = row0 < M, v1 = row1 < M;
#pragma unroll
            for (int nt = 0; nt < 8; nt++) {
                int col = wn * 64 + nt * 8 + 2 * t;
                float a0 = leaky(acc[mt][nt][0] + bsv[nt].x);
                float a1 = leaky(acc[mt][nt][1] + bsv[nt].y);
                float a2 = leaky(acc[mt][nt][2] + bsv[nt].x);
                float a3 = leaky(acc[mt][nt][3] + bsv[nt].y);
                if (v0) {
                    *(float2*)(out + (size_t)row0 * DH + col) = make_float2(a0, a1);
                    if (STATS) {
                        sac[nt][0] += a0; sac[nt][1] += a1;
                        qac[nt][0] += a0 * a0; qac[nt][1] += a1 * a1;
                    }
                }
                if (v1) {
                    *(float2*)(out + (size_t)row1 * DH + col) = make_float2(a2, a3);
                    if (STATS) {
                        sac[nt][0] += a2; sac[nt][1] += a3;
                        qac[nt][0] += a2 * a2; qac[nt][1] += a3 * a3;
                    }
                }
            }
        }
        __syncthreads();   // protect sAh/sAl before next tile overwrites
    }

    if (STATS) {
        // block-level reduction of cross-tile register stats, one atomic set
#pragma unroll
        for (int nt = 0; nt < 8; nt++) {
            float s0 = sac[nt][0], s1 = sac[nt][1];
            float q0 = qac[nt][0], q1 = qac[nt][1];
#pragma unroll
            for (int o = 4; o < 32; o <<= 1) {       // reduce over g lanes
                s0 += __shfl_xor_sync(0xffffffffu, s0, o);
                s1 += __shfl_xor_sync(0xffffffffu, s1, o);
                q0 += __shfl_xor_sync(0xffffffffu, q0, o);
                q1 += __shfl_xor_sync(0xffffffffu, q1, o);
            }
            if (lane < 4) {
                int col = wn * 64 + nt * 8 + 2 * lane;
                sS[wm * 128 + col] = s0;  sS[wm * 128 + col + 1] = s1;
                sQ[wm * 128 + col] = q0;  sQ[wm * 128 + col + 1] = q1;
            }
        }
        __syncthreads();
        if (tid < 128) {
            atomicAdd(sumBuf + tid, sS[tid] + sS[128 + tid] + sS[256 + tid] + sS[384 + tid]);
        } else {
            int c = tid - 128;
            atomicAdd(sqBuf + c, sQ[c] + sQ[128 + c] + sQ[256 + c] + sQ[384 + c]);
        }
    }
}

// ---------------- pooling ----------------------------------------------------
__global__ __launch_bounds__(128) void k_pool(const float* __restrict__ x) {
    int g = blockIdx.x, c = threadIdx.x;
    int r0 = g_gstart[g], r1 = g_gstart[g + 1];
    float s = 0.f;
    for (int r = r0; r < r1; r++) s += x[r * DH + c];
    g_pool[g * DH + c] = s;
}

// ---------------- head -------------------------------------------------------
__global__ __launch_bounds__(128) void k_pool_stats(const float* __restrict__ bn_g,
                                                    const float* __restrict__ bn_b) {
    int c = threadIdx.x;
    float s = 0.f, q = 0.f;
    for (int g = 0; g < N_GRAPHS; g++) {
        float v = g_pool[g * DH + c];
        s += v; q += v * v;
    }
    float mean = s / (float)N_GRAPHS;
    float var = q / (float)N_GRAPHS - mean * mean;
    float rstd = rsqrtf(var + BN_EPS);
    float sc = bn_g[c] * rstd;
    g_scale[c] = sc;
    g_shift[c] = bn_b[c] - mean * sc;
    if (c < DL) { g_fsum[c] = 0.f; g_fsq[c] = 0.f; }
}

__global__ __launch_bounds__(64) void k_head2(const float* __restrict__ feats,
                                              const float* __restrict__ fcW,
                                              const float* __restrict__ fcb,
                                              const float* __restrict__ cW1,
                                              const float* __restrict__ cb1,
                                              const float* __restrict__ cW2,
                                              const float* __restrict__ cb2,
                                              const float* __restrict__ fW1,
                                              const float* __restrict__ fb1) {
    __shared__ float cat[DL + 8];
    __shared__ float t8[8];
    int g = blockIdx.x, j = threadIdx.x;
    if (j < 8) {
        float s = cb1[j];
        for (int i = 0; i < 7; i++) s += feats[g * 7 + i] * cW1[i * 8 + j];
        t8[j] = fmaxf(s, 0.f);
    }
    __syncthreads();
    if (j < 8) {
        float s = cb2[j];
        for (int i = 0; i < 8; i++) s += t8[i] * cW2[i * 8 + j];
        cat[DL + j] = s;
    }
    float o = fcb[j];
    for (int k = 0; k < DH; k++) {
        float a = g_pool[g * DH + k] * g_scale[k] + g_shift[k];
        o += a * fcW[k * DL + j];
    }
    cat[j] = o;
    __syncthreads();
    float s = fb1[j];
    for (int k = 0; k < DL + 8; k++) s += cat[k] * fW1[k * DL + j];
    float v = leaky(s);
    g_f1[g * DL + j] = v;
    atomicAdd(&g_fsum[j], v);
    atomicAdd(&g_fsq[j], v * v);
}

__global__ __launch_bounds__(64) void k_head4(const float* __restrict__ f_g,
                                              const float* __restrict__ f_b,
                                              const float* __restrict__ fW2,
                                              const float* __restrict__ fb2,
                                              float* __restrict__ out) {
    __shared__ float fsc[DL], fsh[DL];
    int g = blockIdx.x, j = threadIdx.x;
    {
        float mean = g_fsum[j] / (float)N_GRAPHS;
        float var = g_fsq[j] / (float)N_GRAPHS - mean * mean;
        float rstd = rsqrtf(var + BN_EPS);
        float sc = f_g[j] * rstd;
        fsc[j] = sc;
        fsh[j] = f_b[j] - mean * sc;
    }
    __syncthreads();
    float s = fb2[j];
    for (int k = 0; k < DL; k++) {
        float a = g_f1[g * DL + k] * fsc[k] + fsh[k];
        s += a * fW2[k * DL + j];
    }
    out[g * DL + j] = s;
}

// ---------------- launch -----------------------------------------------------
extern "C" void kernel_launch(void* const* d_in, const int* in_sizes, int n_in,
                              void* d_out, int out_size) {
    (void)in_sizes; (void)n_in; (void)out_size;
    const float* x      = (const float*)d_in[0];
    const int*   ei     = (const int*)  d_in[1];
    const int*   batch  = (const int*)  d_in[2];
    const float* feats  = (const float*)d_in[3];
    const float* convW1 = (const float*)d_in[4];
    const float* convb1 = (const float*)d_in[5];
    const float* convg1 = (const float*)d_in[6];
    const float* convbb1= (const float*)d_in[7];
    const float* convW2 = (const float*)d_in[8];
    const float* convb2 = (const float*)d_in[9];
    const float* bn_g   = (const float*)d_in[10];
    const float* bn_b   = (const float*)d_in[11];
    const float* fcW    = (const float*)d_in[12];
    const float* fcb    = (const float*)d_in[13];
    const float* cW1    = (const float*)d_in[14];
    const float* cb1    = (const float*)d_in[15];
    const float* cW2    = (const float*)d_in[16];
    const float* cb2    = (const float*)d_in[17];
    const float* fW1    = (const float*)d_in[18];
    const float* fb1    = (const float*)d_in[19];
    const float* f_g    = (const float*)d_in[20];
    const float* f_b    = (const float*)d_in[21];
    const float* fW2    = (const float*)d_in[22];
    const float* fb2    = (const float*)d_in[23];
    float* out = (float*)d_out;

    static bool init_done = false;
    static cudaStream_t s2 = nullptr;
    static cudaEvent_t evFork = nullptr, evJoin0 = nullptr;
    if (!init_done) {
        cudaFuncSetAttribute(k_mma<false, true>,
                             cudaFuncAttributeMaxDynamicSharedMemorySize, MMA_SMEM);
        cudaFuncSetAttribute(k_mma<true, false>,
                             cudaFuncAttributeMaxDynamicSharedMemorySize, MMA_SMEM);
        cudaStreamCreateWithFlags(&s2, cudaStreamNonBlocking);
        cudaEventCreateWithFlags(&evFork, cudaEventDisableTiming);
        cudaEventCreateWithFlags(&evJoin0, cudaEventDisableTiming);
        init_done = true;
    }

    float *dxa, *dxb, *dh0, *dt, *dstats;
    int *dcnt;
    unsigned short *dwh, *dwl;
    cudaGetSymbolAddress((void**)&dxa, g_xa);
    cudaGetSymbolAddress((void**)&dxb, g_xb);
    cudaGetSymbolAddress((void**)&dh0, g_h0);
    cudaGetSymbolAddress((void**)&dt,  g_t);
    cudaGetSymbolAddress((void**)&dstats, g_stats);
    cudaGetSymbolAddress((void**)&dcnt, g_cnt);
    cudaGetSymbolAddress((void**)&dwh, g_wbh);
    cudaGetSymbolAddress((void**)&dwl, g_wbl);

    // fork: side stream handles weight conversion + graph-start search
    cudaEventRecord(evFork, 0);
    cudaStreamWaitEvent(s2, evFork, 0);
    k_wconv<<<6, 256, 0, s2>>>(convW1, convW2);
    k_gstart_bs<<<3, 256, 0, s2>>>(batch);
    cudaEventRecord(evJoin0, s2);

    // main stream: CSR build (coalesced 3-phase scan)
    cudaMemsetAsync(dcnt, 0, N_NODES * sizeof(int));
    cudaMemsetAsync(dstats, 0, N_LAYERS * 2 * DH * sizeof(float));
    k_hist<<<(N_EDGES + 255) / 256, 256>>>(ei);
    k_scanA<<<SCAN_BLOCKS, 1024>>>();
    k_scanB<<<1, 128>>>();
    k_scanC<<<SCAN_BLOCKS, 1024>>>();
    k_fill<<<(N_EDGES + 255) / 256, 256>>>(ei);

    // join side stream before GEMMs (wconv) and pooling (gstart)
    cudaStreamWaitEvent(0, evJoin0, 0);

    const int AGG_GRID = (N_NODES * 32 + 255) / 256;
    const float invM = 1.0f / (float)N_NODES;

    float* xouts[3] = {dxa, dxb, dxa};
    const float* xin = x;

    for (int l = 0; l < N_LAYERS; l++) {
        float* sumB = dstats + l * 2 * DH;
        float* sqB  = sumB + DH;
        k_agg<<<AGG_GRID, 256>>>(xin);
        k_mma<false, true><<<PBLOCKS, 256, MMA_SMEM>>>(
            dh0, dwh + (l * 2) * WTILE, dwl + (l * 2) * WTILE,
            convb1 + l * DH, dt, sumB, sqB,
            nullptr, nullptr, invM, N_NODES);
        k_mma<true, false><<<PBLOCKS, 256, MMA_SMEM>>>(
            dt, dwh + (l * 2 + 1) * WTILE, dwl + (l * 2 + 1) * WTILE,
            convb2 + l * DH, xouts[l], sumB, sqB,
            convg1 + l * DH, convbb1 + l * DH, invM, N_NODES);
        xin = xouts[l];
    }

    // pooling via sorted-batch ranges (atomic-free)
    k_pool<<<N_GRAPHS, 128>>>(xin);

    // head
    k_pool_stats<<<1, 128>>>(bn_g, bn_b);
    k_head2<<<N_GRAPHS, 64>>>(feats, fcW, fcb, cW1, cb1, cW2, cb2, fW1, fb1);
    k_head4<<<N_GRAPHS, 64>>>(f_g, f_b, fW2, fb2, out);
}